// round 3
// baseline (speedup 1.0000x reference)
#include <cuda_runtime.h>
#include <cuda_bf16.h>

// Problem constants (fixed by the dataset)
#define NN 50000
#define EE 500000
#define DD 64      // node feature dim (== hidden dim H)
#define KK 4       // edge feature dim
#define HH 64      // hidden
#define CC 40      // classes
#define PCOLS 256  // K*H

// Scratch (static __device__ arrays are the allowed scratch mechanism)
__device__ float g_P[NN * PCOLS];   // per-node precomputed P[n, k*H + h]
__device__ float g_h[NN * HH];      // hidden node features between layers
__device__ float g_s[NN * HH];      // scatter accumulation buffer
__device__ float g_cnt[NN];         // in-degree (float)

// ---------------------------------------------------------------------------
// In-degree: cnt[dst[e]] += 1
// ---------------------------------------------------------------------------
__global__ void degree_kernel(const int* __restrict__ dst, float* __restrict__ cnt, int E) {
    int e = blockIdx.x * blockDim.x + threadIdx.x;
    if (e < E) atomicAdd(&cnt[dst[e]], 1.0f);
}

// ---------------------------------------------------------------------------
// P = A[N,64] @ B[64,256]  where B[d, k*64+h] = W[(k*64+d)*64 + h]
// Tile: 64 rows x 256 cols, full K=64. 256 threads, 8x8 register blocking.
// smem: As[64][64] (16KB) + Bs[64][256] (64KB) = 80KB dynamic.
// Warp = row-group (A reads broadcast), lanes = col-groups (B reads coalesced).
// ---------------------------------------------------------------------------
__global__ __launch_bounds__(256) void gemm_p_kernel(
    const float* __restrict__ A, const float* __restrict__ W,
    float* __restrict__ Pout, int Nrows)
{
    extern __shared__ float sm[];
    float* As = sm;          // 64*64
    float* Bs = sm + 4096;   // 64*256

    const int tid = threadIdx.x;
    const int rt = tid >> 5;   // warp id 0..7 -> rows rt*8..rt*8+7
    const int ct = tid & 31;   // lane -> cols ct*8..ct*8+7
    const int row0 = blockIdx.x * 64;

    // Load B (reshaped/permuted W): coalesced read of W, permuted store
    for (int idx = tid; idx < KK * DD * HH; idx += 256) {
        int k = idx >> 12;
        int d = (idx >> 6) & 63;
        int h = idx & 63;
        Bs[d * 256 + k * 64 + h] = W[idx];
    }

    // Load A tile (64 rows x 64 cols) via float4
    #pragma unroll
    for (int i = 0; i < 4; i++) {
        int f4i = tid + i * 256;       // 0..1023
        int r = f4i >> 4;
        int c4 = f4i & 15;
        float4 v = make_float4(0.f, 0.f, 0.f, 0.f);
        if (row0 + r < Nrows)
            v = reinterpret_cast<const float4*>(A)[(size_t)(row0 + r) * 16 + c4];
        float* p = &As[r * 64 + c4 * 4];
        p[0] = v.x; p[1] = v.y; p[2] = v.z; p[3] = v.w;
    }
    __syncthreads();

    float acc[8][8];
    #pragma unroll
    for (int i = 0; i < 8; i++)
        #pragma unroll
        for (int j = 0; j < 8; j++) acc[i][j] = 0.f;

    #pragma unroll 4
    for (int d = 0; d < 64; d++) {
        float ar[8], br[8];
        #pragma unroll
        for (int i = 0; i < 8; i++) ar[i] = As[(rt * 8 + i) * 64 + d];  // broadcast per warp
        #pragma unroll
        for (int j = 0; j < 8; j++) br[j] = Bs[d * 256 + ct * 8 + j];   // coalesced
        #pragma unroll
        for (int i = 0; i < 8; i++)
            #pragma unroll
            for (int j = 0; j < 8; j++) acc[i][j] += ar[i] * br[j];
    }

    // Store P tile
    #pragma unroll
    for (int i = 0; i < 8; i++) {
        int r = row0 + rt * 8 + i;
        if (r < Nrows) {
            float4 v0 = make_float4(acc[i][0], acc[i][1], acc[i][2], acc[i][3]);
            float4 v1 = make_float4(acc[i][4], acc[i][5], acc[i][6], acc[i][7]);
            float4* op = reinterpret_cast<float4*>(Pout + (size_t)r * 256 + ct * 8);
            op[0] = v0;
            op[1] = v1;
        }
    }
}

// ---------------------------------------------------------------------------
// Edge kernel: 16 lanes per edge, lane covers 4 contiguous h-columns.
// m[h] = relu(b[h] + sum_k e_k * P[src, k*64+h]);  s[dst, h] += m[h] (v4 red)
// ---------------------------------------------------------------------------
__global__ void edge_kernel(
    const float* __restrict__ ef, const int* __restrict__ src,
    const int* __restrict__ dst, const float* __restrict__ Pm,
    const float* __restrict__ bias, float* __restrict__ sout, int E)
{
    int gt = blockIdx.x * blockDim.x + threadIdx.x;
    int e = gt >> 4;
    int lane = gt & 15;
    if (e >= E) return;

    int sn = src[e];
    int tn = dst[e];
    float4 ev = reinterpret_cast<const float4*>(ef)[e];

    const float4* Pr = reinterpret_cast<const float4*>(Pm + (size_t)sn * 256);
    float4 p0 = Pr[lane];
    float4 p1 = Pr[16 + lane];
    float4 p2 = Pr[32 + lane];
    float4 p3 = Pr[48 + lane];
    float4 b4 = reinterpret_cast<const float4*>(bias)[lane];

    float x = fmaxf(b4.x + ev.x * p0.x + ev.y * p1.x + ev.z * p2.x + ev.w * p3.x, 0.f);
    float y = fmaxf(b4.y + ev.x * p0.y + ev.y * p1.y + ev.z * p2.y + ev.w * p3.y, 0.f);
    float z = fmaxf(b4.z + ev.x * p0.z + ev.y * p1.z + ev.z * p2.z + ev.w * p3.z, 0.f);
    float w = fmaxf(b4.w + ev.x * p0.w + ev.y * p1.w + ev.z * p2.w + ev.w * p3.w, 0.f);

    float* outp = sout + (size_t)tn * 64 + lane * 4;
    asm volatile("red.global.add.v4.f32 [%0], {%1, %2, %3, %4};"
                 :: "l"(outp), "f"(x), "f"(y), "f"(z), "f"(w)
                 : "memory");
}

// ---------------------------------------------------------------------------
// Node update: h = relu(s / max(cnt,1)), vectorized float4
// ---------------------------------------------------------------------------
__global__ void node_kernel(const float* __restrict__ s, const float* __restrict__ cnt,
                            float* __restrict__ hout, int total4)
{
    int i = blockIdx.x * blockDim.x + threadIdx.x;
    if (i >= total4) return;
    int n = i >> 4;
    float inv = 1.0f / fmaxf(cnt[n], 1.0f);
    float4 v = reinterpret_cast<const float4*>(s)[i];
    v.x = fmaxf(v.x * inv, 0.f);
    v.y = fmaxf(v.y * inv, 0.f);
    v.z = fmaxf(v.z * inv, 0.f);
    v.w = fmaxf(v.w * inv, 0.f);
    reinterpret_cast<float4*>(hout)[i] = v;
}

// ---------------------------------------------------------------------------
// Final layer: h2 = relu(s/cnt) fused with out = h2 @ Wfc + bfc
// Block: 256 threads, 32 nodes. smem: hr[32*64], Wfc[64*40], bfc[40]
// ---------------------------------------------------------------------------
__global__ __launch_bounds__(256) void node_fc_kernel(
    const float* __restrict__ s, const float* __restrict__ cnt,
    const float* __restrict__ Wfc, const float* __restrict__ bfc,
    float* __restrict__ out, int Nn)
{
    __shared__ float hr[32 * 64];
    __shared__ float Wf[64 * 40];
    __shared__ float bf[40];

    const int tid = threadIdx.x;
    const int base = blockIdx.x * 32;

    for (int i = tid; i < 64 * 40; i += 256) Wf[i] = Wfc[i];
    if (tid < 40) bf[tid] = bfc[tid];

    // Phase 1: compute relu(s/cnt) rows into smem (float4)
    #pragma unroll
    for (int it = 0; it < 2; it++) {
        int i = tid + it * 256;        // 0..511 -> 32 nodes * 16 f4
        int n = i >> 4;
        int gn = base + n;
        float4 v = make_float4(0.f, 0.f, 0.f, 0.f);
        if (gn < Nn) {
            float inv = 1.0f / fmaxf(cnt[gn], 1.0f);
            v = reinterpret_cast<const float4*>(s)[(size_t)gn * 16 + (i & 15)];
            v.x = fmaxf(v.x * inv, 0.f);
            v.y = fmaxf(v.y * inv, 0.f);
            v.z = fmaxf(v.z * inv, 0.f);
            v.w = fmaxf(v.w * inv, 0.f);
        }
        reinterpret_cast<float4*>(hr)[i] = v;
    }
    __syncthreads();

    // Phase 2: each thread handles one node (n = tid/8) and 5 classes
    int n = tid >> 3;
    int cg = tid & 7;
    int gn = base + n;
    float acc[5];
    #pragma unroll
    for (int q = 0; q < 5; q++) acc[q] = bf[cg * 5 + q];

    #pragma unroll 8
    for (int h = 0; h < 64; h++) {
        float a = hr[n * 64 + h];
        #pragma unroll
        for (int q = 0; q < 5; q++) acc[q] += a * Wf[h * 40 + cg * 5 + q];
    }
    if (gn < Nn) {
        #pragma unroll
        for (int q = 0; q < 5; q++) out[(size_t)gn * 40 + cg * 5 + q] = acc[q];
    }
}

// ---------------------------------------------------------------------------
extern "C" void kernel_launch(void* const* d_in, const int* in_sizes, int n_in,
                              void* d_out, int out_size)
{
    const float* node_features = (const float*)d_in[0];
    const float* edge_features = (const float*)d_in[1]; // [2, E, 4]
    const int*   src           = (const int*)d_in[2];
    const int*   dst           = (const int*)d_in[3];
    const float* W0            = (const float*)d_in[4];
    const float* b0            = (const float*)d_in[5];
    const float* W1            = (const float*)d_in[6];
    const float* b1            = (const float*)d_in[7];
    const float* Wfc           = (const float*)d_in[8];
    const float* bfc           = (const float*)d_in[9];
    float* out = (float*)d_out;

    float *Pp, *hp, *sp, *cp;
    cudaGetSymbolAddress((void**)&Pp, g_P);
    cudaGetSymbolAddress((void**)&hp, g_h);
    cudaGetSymbolAddress((void**)&sp, g_s);
    cudaGetSymbolAddress((void**)&cp, g_cnt);

    const int gemm_smem = (64 * 64 + 64 * 256) * (int)sizeof(float); // 80KB
    cudaFuncSetAttribute(gemm_p_kernel, cudaFuncAttributeMaxDynamicSharedMemorySize, gemm_smem);

    const int gemm_blocks = (NN + 63) / 64;
    const int edge_blocks = (EE * 16 + 255) / 256;
    const int node_blocks = (NN * 16 + 255) / 256;

    // degree (same dst for both layers)
    cudaMemsetAsync(cp, 0, NN * sizeof(float), 0);
    degree_kernel<<<(EE + 255) / 256, 256>>>(dst, cp, EE);

    // Layer 0
    cudaMemsetAsync(sp, 0, (size_t)NN * HH * sizeof(float), 0);
    gemm_p_kernel<<<gemm_blocks, 256, gemm_smem>>>(node_features, W0, Pp, NN);
    edge_kernel<<<edge_blocks, 256>>>(edge_features, src, dst, Pp, b0, sp, EE);
    node_kernel<<<node_blocks, 256>>>(sp, cp, hp, NN * 16);

    // Layer 1 + fused FC
    cudaMemsetAsync(sp, 0, (size_t)NN * HH * sizeof(float), 0);
    gemm_p_kernel<<<gemm_blocks, 256, gemm_smem>>>(hp, W1, Pp, NN);
    edge_kernel<<<edge_blocks, 256>>>(edge_features + (size_t)EE * KK, src, dst, Pp, b1, sp, EE);
    node_fc_kernel<<<(NN + 31) / 32, 256>>>(sp, cp, Wfc, bfc, out, NN);
}